// round 13
// baseline (speedup 1.0000x reference)
#include <cuda_runtime.h>

#define Dm 1024
#define MAXB 8

// ---------------- scratch (zero-init at load; consumers reset for replay) ---
__device__ float g_q0[MAXB * Dm];              // Wq acc (zeroed by k3)
__device__ float g_u[MAXB * Dm];               // overwritten fully by k2_u
__device__ float g_xw[MAXB * Dm];              // k3 acc, unnormalized (zeroed by ln2)
__device__ float g_Z[MAXB];                    // softmax denominators (zeroed by ln2)
__device__ float g_r[MAXB * Dm];               // overwritten fully by k5
__device__ float g_accV[MAXB * Dm];            // Wv acc (zeroed by ln2)
__device__ float g_accD[MAXB * Dm];            // Wd acc (zeroed by ln2)

// ---------------- block reductions ------------------------------------------
__device__ __forceinline__ float blk_reduce(float v, volatile float* sbuf) {
    int lane = threadIdx.x & 31, w = threadIdx.x >> 5;
#pragma unroll
    for (int o = 16; o; o >>= 1) v += __shfl_xor_sync(0xffffffffu, v, o);
    __syncthreads();
    if (lane == 0) sbuf[w] = v;
    __syncthreads();
    int nw = blockDim.x >> 5;
    if (w == 0) {
        float r = (lane < nw) ? sbuf[lane] : 0.f;
#pragma unroll
        for (int o = 16; o; o >>= 1) r += __shfl_xor_sync(0xffffffffu, r, o);
        if (lane == 0) sbuf[0] = r;
    }
    __syncthreads();
    return sbuf[0];
}

// ---------------- PDL skinny GEMV: acc[b,j] += A[b,d0:d0+32] @ W -------------
// grid (8, 32), block 128 (256 blocks). W tile preloaded to regs BEFORE
// gridsync. Target buffer must be zero on entry.
__global__ void __launch_bounds__(128) gemv_pdl(const float* __restrict__ A,
                                                long astride,
                                                const float* __restrict__ W,
                                                float* __restrict__ accout, int B) {
    __shared__ float as[MAXB][32];
    int tid = threadIdx.x;
    int j  = blockIdx.x * 128 + tid;
    int d0 = blockIdx.y * 32;
    float wv[32];
#pragma unroll
    for (int dd = 0; dd < 32; dd++) wv[dd] = W[(long)(d0 + dd) * Dm + j];
    cudaGridDependencySynchronize();
    for (int i = tid; i < MAXB * 32; i += 128) {
        int b = i >> 5, dd = i & 31;
        as[b][dd] = (b < B) ? A[(long)b * astride + d0 + dd] : 0.f;
    }
    __syncthreads();
    float acc[MAXB];
#pragma unroll
    for (int b = 0; b < MAXB; b++) acc[b] = 0.f;
#pragma unroll
    for (int dd = 0; dd < 32; dd++) {
#pragma unroll
        for (int b = 0; b < MAXB; b++) acc[b] = fmaf(as[b][dd], wv[dd], acc[b]);
    }
    for (int b = 0; b < B; b++)
        atomicAdd(&accout[(long)b * Dm + j], acc[b]);
}

// ---------------- u[b,d] = Wk[d,:] . (q0[b,:] + bq) --------------------------
// 128 blocks x 8 warps (1 row each). Wk row preloaded to regs before gridsync.
__global__ void __launch_bounds__(256) k2_u(const float* __restrict__ Wk,
                                            const float* __restrict__ q0g,
                                            const float* __restrict__ bq,
                                            float* __restrict__ u) {
    __shared__ float4 q0s[MAXB * 256];               // 32 KB
    int wid = threadIdx.x >> 5, lane = threadIdx.x & 31;
    int d = blockIdx.x * 8 + wid;
    const float4* wrow = (const float4*)(Wk + (long)d * Dm);
    float4 wv[8];
#pragma unroll
    for (int i = 0; i < 8; i++) wv[i] = wrow[lane + 32 * i];
    cudaGridDependencySynchronize();
    for (int i = threadIdx.x; i < MAXB * 256; i += 256) {
        float4 q = ((const float4*)q0g)[i];
        float4 bb = ((const float4*)bq)[i & 255];
        q.x += bb.x; q.y += bb.y; q.z += bb.z; q.w += bb.w;
        q0s[i] = q;
    }
    __syncthreads();
    float acc[MAXB];
#pragma unroll
    for (int b = 0; b < MAXB; b++) acc[b] = 0.f;
#pragma unroll
    for (int i = 0; i < 8; i++) {
#pragma unroll
        for (int b = 0; b < MAXB; b++) {
            float4 q = q0s[b * 256 + lane + 32 * i];
            acc[b] += wv[i].x * q.x + wv[i].y * q.y + wv[i].z * q.z + wv[i].w * q.w;
        }
    }
#pragma unroll
    for (int b = 0; b < MAXB; b++)
#pragma unroll
        for (int o = 16; o; o >>= 1)
            acc[b] += __shfl_xor_sync(0xffffffffu, acc[b], o);
    if (lane == 0)
#pragma unroll
        for (int b = 0; b < MAXB; b++) u[(long)b * Dm + d] = acc[b];
}

// ---------------- k3: fused single-pass attention ----------------------------
// grid (S/32, B) = 512 blocks, 256 thr, 4 tokens/warp.
// p_t = exp(x_t.u / 32)   [no max-subtraction: scores ~N(0,1), exp safe]
// xw_un[b,:] += sum_t p_t x_t ;  Z[b] += sum_t p_t.   x read ONCE, in registers.
__global__ void __launch_bounds__(256) k3_fused(const float* __restrict__ x,
                                                const float* __restrict__ ug,
                                                float* __restrict__ q0reset,
                                                float* __restrict__ xw,
                                                float* __restrict__ Zg, int S) {
    __shared__ float4 us[256];                        // 4 KB
    __shared__ float4 mb[8][256];                     // 32 KB merge
    __shared__ float zp[8];
    int b = blockIdx.y;
    int tid = threadIdx.x, wid = tid >> 5, lane = tid & 31;
    int tbase = blockIdx.x * 32 + wid * 4;
    const float4* x0 = (const float4*)x + ((long)b * S + tbase) * 256;
#pragma unroll
    for (int i = 0; i < 8; i++)
        asm volatile("prefetch.global.L2 [%0];" :: "l"(x0 + lane + 32 * i));
    cudaGridDependencySynchronize();
    if (blockIdx.x == 0)                              // zero q0[b,:] for next run
        ((float4*)q0reset)[b * 256 + tid] = make_float4(0.f, 0.f, 0.f, 0.f);
    us[tid] = ((const float4*)(ug + (long)b * Dm))[tid];
    __syncthreads();

    float4 acc[8];
#pragma unroll
    for (int i = 0; i < 8; i++) acc[i] = make_float4(0.f, 0.f, 0.f, 0.f);
    float zsum = 0.f;

#pragma unroll
    for (int k = 0; k < 4; k++) {
        const float4* xr = x0 + (long)k * 256;
        float4 xv[8];
#pragma unroll
        for (int i = 0; i < 8; i++) xv[i] = xr[lane + 32 * i];
        float d = 0.f;
#pragma unroll
        for (int i = 0; i < 8; i++) {
            float4 uv = us[lane + 32 * i];
            d += xv[i].x * uv.x + xv[i].y * uv.y + xv[i].z * uv.z + xv[i].w * uv.w;
        }
#pragma unroll
        for (int o = 16; o; o >>= 1) d += __shfl_xor_sync(0xffffffffu, d, o);
        float p = __expf(d * 0.03125f);               // 1/sqrt(1024)
        zsum += p;
#pragma unroll
        for (int i = 0; i < 8; i++) {
            acc[i].x = fmaf(p, xv[i].x, acc[i].x);
            acc[i].y = fmaf(p, xv[i].y, acc[i].y);
            acc[i].z = fmaf(p, xv[i].z, acc[i].z);
            acc[i].w = fmaf(p, xv[i].w, acc[i].w);
        }
    }

    if (lane == 0) zp[wid] = zsum;
#pragma unroll
    for (int i = 0; i < 8; i++) mb[wid][lane + 32 * i] = acc[i];
    __syncthreads();

    float4 tot = mb[0][tid];
#pragma unroll
    for (int w = 1; w < 8; w++) {
        float4 v = mb[w][tid];
        tot.x += v.x; tot.y += v.y; tot.z += v.z; tot.w += v.w;
    }
    float* dst = &xw[(long)b * Dm + tid * 4];
    atomicAdd(dst + 0, tot.x);
    atomicAdd(dst + 1, tot.y);
    atomicAdd(dst + 2, tot.z);
    atomicAdd(dst + 3, tot.w);
    if (tid == 0) {
        float zb = 0.f;
#pragma unroll
        for (int w = 0; w < 8; w++) zb += zp[w];
        atomicAdd(&Zg[b], zb);
    }
}

// ---------------- k5: fused LN1 + gemv(Wd) ------------------------------------
// grid (4, 32), 256 thr (128 blocks). Per block: redundant LN1 over
// v = accV/Z + bv + x0 (warp-per-b, pure shfl), r-slice for d-chunk in smem,
// then accD[b,j] += r_slice . Wd[d0:d0+32, j]. jx==0 blocks materialize r.
__global__ void __launch_bounds__(256) k5_lngemv(const float* __restrict__ accV,
                                                 const float* __restrict__ x, long xstride,
                                                 const float* __restrict__ bv,
                                                 const float* __restrict__ g1,
                                                 const float* __restrict__ b1,
                                                 const float* __restrict__ Zg,
                                                 const float* __restrict__ Wd,
                                                 float* __restrict__ rout,
                                                 float* __restrict__ accD) {
    __shared__ float rs[MAXB][32];
    int tid = threadIdx.x;
    int jx = blockIdx.x, dc = blockIdx.y;
    int j = jx * 256 + tid, d0 = dc * 32;
    int b = tid >> 5, seg = tid & 31;                 // warp == batch row

    // heavy preload only: Wd tile (overlaps upstream under PDL)
    float wv[32];
#pragma unroll
    for (int k = 0; k < 32; k++) wv[k] = Wd[(long)(d0 + k) * Dm + j];
    cudaGridDependencySynchronize();

    float zinv = 1.f / Zg[b];
    // LN1 stats: lanes of warp b cover its 1024-row in 32-float segments
    float s1 = 0.f, s2 = 0.f;
    {
        const float4* av = (const float4*)(accV + (long)b * Dm) + seg * 8;
        const float4* bvv = (const float4*)bv + seg * 8;
        const float4* xvv = (const float4*)(x + (long)b * xstride) + seg * 8;
#pragma unroll
        for (int k = 0; k < 8; k++) {
            float4 a = av[k], bb4 = bvv[k], x4 = xvv[k];
            float v0 = fmaf(a.x, zinv, bb4.x + x4.x);
            float v1 = fmaf(a.y, zinv, bb4.y + x4.y);
            float v2 = fmaf(a.z, zinv, bb4.z + x4.z);
            float v3 = fmaf(a.w, zinv, bb4.w + x4.w);
            s1 += v0 + v1 + v2 + v3;
            s2 += v0 * v0 + v1 * v1 + v2 * v2 + v3 * v3;
        }
#pragma unroll
        for (int o = 16; o; o >>= 1) {
            s1 += __shfl_xor_sync(0xffffffffu, s1, o);
            s2 += __shfl_xor_sync(0xffffffffu, s2, o);
        }
    }
    float mu = s1 * (1.f / Dm);
    float var = s2 * (1.f / Dm) - mu * mu;
    float rstd = rsqrtf(var + 1e-5f);

    // r slice for this d-chunk (thread (b,seg) -> d = d0+seg)
    {
        float v = fmaf(accV[(long)b * Dm + d0 + seg], zinv,
                       bv[d0 + seg] + x[(long)b * xstride + d0 + seg]);
        float rv = (v - mu) * rstd * g1[d0 + seg] + b1[d0 + seg];
        rs[b][seg] = rv;
        if (jx == 0) rout[(long)b * Dm + d0 + seg] = rv;
    }
    __syncthreads();

    // gemv: accD[bb,j] += rs[bb,:] . wv[:]
    float acc[MAXB];
#pragma unroll
    for (int bb = 0; bb < MAXB; bb++) acc[bb] = 0.f;
#pragma unroll
    for (int dd = 0; dd < 32; dd++) {
#pragma unroll
        for (int bb = 0; bb < MAXB; bb++) acc[bb] = fmaf(rs[bb][dd], wv[dd], acc[bb]);
    }
#pragma unroll
    for (int bb = 0; bb < MAXB; bb++)
        atomicAdd(&accD[(long)bb * Dm + j], acc[bb]);
}

// ---------------- ln2: out = LN2(relu(accD+bd)+r)@Wc + bc; reset all accs ----
__global__ void __launch_bounds__(1024) k_ln2(float* __restrict__ acc,
                                              const float* __restrict__ bd,
                                              const float* __restrict__ r,
                                              const float* __restrict__ g2,
                                              const float* __restrict__ b2,
                                              const float* __restrict__ Wc,
                                              const float* __restrict__ bc,
                                              float* __restrict__ accVz,
                                              float* __restrict__ xwz,
                                              float* __restrict__ Zg,
                                              float* __restrict__ out) {
    int b = blockIdx.x, j = threadIdx.x;
    __shared__ float sbuf[32];
    float gg = g2[j], bb = b2[j], bdj = bd[j];
    float w0 = Wc[j * 2 + 0], w1 = Wc[j * 2 + 1];
    cudaGridDependencySynchronize();
    float v = fmaxf(acc[(long)b * Dm + j] + bdj, 0.f) + r[(long)b * Dm + j];
    acc[(long)b * Dm + j]   = 0.f;                    // resets for next replay
    accVz[(long)b * Dm + j] = 0.f;
    xwz[(long)b * Dm + j]   = 0.f;
    if (j == 0) Zg[b] = 0.f;
    float sum = blk_reduce(v, sbuf);
    float sq  = blk_reduce(v * v, sbuf);
    float mu  = sum * (1.f / Dm);
    float var = sq * (1.f / Dm) - mu * mu;
    float rstd = rsqrtf(var + 1e-5f);
    float h = (v - mu) * rstd * gg + bb;
    float l0 = blk_reduce(h * w0, sbuf);
    float l1 = blk_reduce(h * w1, sbuf);
    if (j == 0) {
        out[b * 2 + 0] = l0 + bc[0];
        out[b * 2 + 1] = l1 + bc[1];
    }
}

// ---------------- host --------------------------------------------------------
static void launch_ex(const void* fn, dim3 grid, dim3 block, void** args, bool pdl) {
    cudaLaunchConfig_t cfg = {};
    cfg.gridDim = grid;
    cfg.blockDim = block;
    cfg.dynamicSmemBytes = 0;
    cfg.stream = 0;
    cudaLaunchAttribute attr[1];
    attr[0].id = cudaLaunchAttributeProgrammaticStreamSerialization;
    attr[0].val.programmaticStreamSerializationAllowed = 1;
    cfg.attrs = attr;
    cfg.numAttrs = pdl ? 1 : 0;
    cudaLaunchKernelExC(&cfg, fn, args);
}

extern "C" void kernel_launch(void* const* d_in, const int* in_sizes, int n_in,
                              void* d_out, int out_size) {
    const float* x  = (const float*)d_in[0];
    const float* Wq = (const float*)d_in[1];
    const float* bq = (const float*)d_in[2];
    const float* Wk = (const float*)d_in[3];
    // d_in[4] = bk: constant over t in scores -> cancels in softmax; unused.
    const float* Wv = (const float*)d_in[5];
    const float* bv = (const float*)d_in[6];
    const float* Wd = (const float*)d_in[7];
    const float* bd = (const float*)d_in[8];
    const float* g1 = (const float*)d_in[9];
    const float* b1 = (const float*)d_in[10];
    const float* g2 = (const float*)d_in[11];
    const float* b2 = (const float*)d_in[12];
    const float* Wc = (const float*)d_in[13];
    const float* bc = (const float*)d_in[14];
    float* out = (float*)d_out;

    int  B   = out_size / 2;                       // 8
    long xsz = (long)in_sizes[0];
    int  S   = (int)(xsz / ((long)B * Dm));        // 2048
    long xstride = (long)S * Dm;

    float *q0, *u, *xw, *r, *accV, *accD, *Z;
    cudaGetSymbolAddress((void**)&q0,   g_q0);
    cudaGetSymbolAddress((void**)&u,    g_u);
    cudaGetSymbolAddress((void**)&xw,   g_xw);
    cudaGetSymbolAddress((void**)&r,    g_r);
    cudaGetSymbolAddress((void**)&accV, g_accV);
    cudaGetSymbolAddress((void**)&accD, g_accD);
    cudaGetSymbolAddress((void**)&Z,    g_Z);

    // 1. q0 += x0 @ Wq   (first kernel: no PDL wait; starts loading at t=0)
    {
        void* a[] = {(void*)&x, (void*)&xstride, (void*)&Wq, (void*)&q0, (void*)&B};
        launch_ex((const void*)gemv_pdl, dim3(8, 32), dim3(128), a, false);
    }
    // 2. u = Wk @ (q0 + bq)
    {
        void* a[] = {(void*)&Wk, (void*)&q0, (void*)&bq, (void*)&u};
        launch_ex((const void*)k2_u, dim3(Dm / 8), dim3(256), a, true);
    }
    // 3. fused attention pass: xw_un, Z (also zeroes q0)
    {
        void* a[] = {(void*)&x, (void*)&u, (void*)&q0, (void*)&xw, (void*)&Z, (void*)&S};
        launch_ex((const void*)k3_fused, dim3(S / 32, B), dim3(256), a, true);
    }
    // 4. accV += xw_un @ Wv
    {
        long st = Dm;
        void* a[] = {(void*)&xw, (void*)&st, (void*)&Wv, (void*)&accV, (void*)&B};
        launch_ex((const void*)gemv_pdl, dim3(8, 32), dim3(128), a, true);
    }
    // 5. fused: r = LN1(accV/Z + bv + x0); accD += r @ Wd
    {
        void* a[] = {(void*)&accV, (void*)&x, (void*)&xstride, (void*)&bv,
                     (void*)&g1, (void*)&b1, (void*)&Z, (void*)&Wd,
                     (void*)&r, (void*)&accD};
        launch_ex((const void*)k5_lngemv, dim3(4, 32), dim3(256), a, true);
    }
    // 6. out = LN2(relu(accD + bd) + r) @ Wc + bc; reset accD/accV/xw/Z
    {
        void* a[] = {(void*)&accD, (void*)&bd, (void*)&r, (void*)&g2, (void*)&b2,
                     (void*)&Wc, (void*)&bc, (void*)&accV, (void*)&xw, (void*)&Z,
                     (void*)&out};
        launch_ex((const void*)k_ln2, dim3(B), dim3(1024), a, true);
    }
}

// round 14
// speedup vs baseline: 1.0051x; 1.0051x over previous
#include <cuda_runtime.h>

#define Dm 1024
#define MAXB 8
#define SMAX 4096

// ---------------- scratch (zero-init at load; consumers reset for replay) ---
__device__ float g_q0[MAXB * Dm];              // Wq acc (zeroed by k3a)
__device__ float g_u[MAXB * Dm];               // overwritten fully by k2_u
__device__ float g_xw[MAXB * Dm];              // k3b acc (zeroed by k_ln1)
__device__ float g_Z[MAXB];                    // softmax denominators (zeroed by k_ln1)
__device__ float g_r[MAXB * Dm];               // overwritten fully by k_ln1
__device__ float g_accV[MAXB * Dm];            // Wv acc (zeroed by k_ln1)
__device__ float g_accD[MAXB * Dm];            // Wd acc (zeroed by k_ln2)
__device__ float g_sc[MAXB * SMAX];            // exp'd scores (overwritten by k3a)

// ---------------- block reductions ------------------------------------------
__device__ __forceinline__ float blk_reduce(float v, volatile float* sbuf) {
    int lane = threadIdx.x & 31, w = threadIdx.x >> 5;
#pragma unroll
    for (int o = 16; o; o >>= 1) v += __shfl_xor_sync(0xffffffffu, v, o);
    __syncthreads();
    if (lane == 0) sbuf[w] = v;
    __syncthreads();
    int nw = blockDim.x >> 5;
    if (w == 0) {
        float r = (lane < nw) ? sbuf[lane] : 0.f;
#pragma unroll
        for (int o = 16; o; o >>= 1) r += __shfl_xor_sync(0xffffffffu, r, o);
        if (lane == 0) sbuf[0] = r;
    }
    __syncthreads();
    return sbuf[0];
}

// ---------------- PDL skinny GEMV: acc[b,j] += A[b,d0:d0+16] @ W -------------
// grid (8, 64), block 128 (512 blocks), 16-deep d-chunks. W tile in regs
// BEFORE gridsync. Target buffer must be zero on entry.
__global__ void __launch_bounds__(128) gemv_pdl(const float* __restrict__ A,
                                                long astride,
                                                const float* __restrict__ W,
                                                float* __restrict__ accout, int B) {
    __shared__ float as[MAXB][16];
    int tid = threadIdx.x;
    int j  = blockIdx.x * 128 + tid;
    int d0 = blockIdx.y * 16;
    float wv[16];
#pragma unroll
    for (int dd = 0; dd < 16; dd++) wv[dd] = W[(long)(d0 + dd) * Dm + j];
    cudaGridDependencySynchronize();
    if (tid < MAXB * 16) {
        int b = tid >> 4, dd = tid & 15;
        as[b][dd] = (b < B) ? A[(long)b * astride + d0 + dd] : 0.f;
    }
    __syncthreads();
    float acc[MAXB];
#pragma unroll
    for (int b = 0; b < MAXB; b++) acc[b] = 0.f;
#pragma unroll
    for (int dd = 0; dd < 16; dd++) {
#pragma unroll
        for (int b = 0; b < MAXB; b++) acc[b] = fmaf(as[b][dd], wv[dd], acc[b]);
    }
    for (int b = 0; b < B; b++)
        atomicAdd(&accout[(long)b * Dm + j], acc[b]);
}

// ---------------- u[b,d] = Wk[d,:] . (q0[b,:] + bq) --------------------------
// 256 blocks x 4 warps (1 row each). Wk row preloaded to regs before gridsync.
__global__ void __launch_bounds__(128) k2_u(const float* __restrict__ Wk,
                                            const float* __restrict__ q0g,
                                            const float* __restrict__ bq,
                                            float* __restrict__ u) {
    __shared__ float4 q0s[MAXB * 256];               // 32 KB
    int wid = threadIdx.x >> 5, lane = threadIdx.x & 31;
    int d = blockIdx.x * 4 + wid;
    const float4* wrow = (const float4*)(Wk + (long)d * Dm);
    float4 wv[8];
#pragma unroll
    for (int i = 0; i < 8; i++) wv[i] = wrow[lane + 32 * i];
    cudaGridDependencySynchronize();
    for (int i = threadIdx.x; i < MAXB * 256; i += 128) {
        float4 q = ((const float4*)q0g)[i];
        float4 bb = ((const float4*)bq)[i & 255];
        q.x += bb.x; q.y += bb.y; q.z += bb.z; q.w += bb.w;
        q0s[i] = q;
    }
    __syncthreads();
    float acc[MAXB];
#pragma unroll
    for (int b = 0; b < MAXB; b++) acc[b] = 0.f;
#pragma unroll
    for (int i = 0; i < 8; i++) {
#pragma unroll
        for (int b = 0; b < MAXB; b++) {
            float4 q = q0s[b * 256 + lane + 32 * i];
            acc[b] += wv[i].x * q.x + wv[i].y * q.y + wv[i].z * q.z + wv[i].w * q.w;
        }
    }
#pragma unroll
    for (int b = 0; b < MAXB; b++)
#pragma unroll
        for (int o = 16; o; o >>= 1)
            acc[b] += __shfl_xor_sync(0xffffffffu, acc[b], o);
    if (lane == 0)
#pragma unroll
        for (int b = 0; b < MAXB; b++) u[(long)b * Dm + d] = acc[b];
}

// ---------------- k3a: score stream, stores p = exp(score) + Z atomics ------
// grid (S/16, B) = 1024 blocks, 256 thr, 2 tokens/warp. No-max softmax:
// scores ~N(0,1) so exp is fp32-safe (validated R12, rel_err 7e-7).
__global__ void __launch_bounds__(256) k3a(const float* __restrict__ x,
                                           const float* __restrict__ ug,
                                           float* __restrict__ q0reset,
                                           float* __restrict__ sc,
                                           float* __restrict__ Zg, int S) {
    __shared__ float zp[8];
    int b = blockIdx.y;
    int tid = threadIdx.x, wid = tid >> 5, lane = tid & 31;
    int tbase = blockIdx.x * 16 + wid * 2;
    const float4* x0 = (const float4*)x + ((long)b * S + tbase) * 256;
#pragma unroll
    for (int k = 0; k < 2; k++)
#pragma unroll
        for (int i = 0; i < 8; i++)
            asm volatile("prefetch.global.L2 [%0];" :: "l"(x0 + k * 256 + lane + 32 * i));
    cudaGridDependencySynchronize();
    if (blockIdx.x == 0)                              // zero q0[b,:] for next run
        ((float4*)q0reset)[b * 256 + tid] = make_float4(0.f, 0.f, 0.f, 0.f);
    const float4* ub = (const float4*)(ug + (long)b * Dm);
    float4 uv[8];
#pragma unroll
    for (int i = 0; i < 8; i++) uv[i] = __ldg(ub + lane + 32 * i);
    float zsum = 0.f;
#pragma unroll
    for (int k = 0; k < 2; k++) {
        const float4* xr = x0 + (long)k * 256;
        float d = 0.f;
#pragma unroll
        for (int i = 0; i < 8; i++) {
            float4 xv = xr[lane + 32 * i];
            d += xv.x * uv[i].x + xv.y * uv[i].y + xv.z * uv[i].z + xv.w * uv[i].w;
        }
#pragma unroll
        for (int o = 16; o; o >>= 1) d += __shfl_xor_sync(0xffffffffu, d, o);
        float p = __expf(d * 0.03125f);               // 1/sqrt(1024)
        zsum += p;
        if (lane == 0) sc[(long)b * S + tbase + k] = p;
    }
    if (lane == 0) zp[wid] = zsum;                    // zsum counted 2x per warp;
    __syncthreads();                                  // lane0 value is correct sum
    if (tid == 0) {
        float zb = 0.f;
#pragma unroll
        for (int w = 0; w < 8; w++) zb += zp[w];
        atomicAdd(&Zg[b], zb);
    }
}

// ---------------- k3b: weighted accumulate (weights precomputed) ------------
// grid ((S/128)*8, B) = 1024 blocks, 256 thr. No reductions, no score rescan.
__global__ void __launch_bounds__(256) k3b(const float* __restrict__ x,
                                           const float* __restrict__ scg,
                                           float* __restrict__ xw, int S) {
    __shared__ float w[128];
    __shared__ float4 redb[8][32];
    int b = blockIdx.y;
    int ntc = S >> 7;                                 // 128-token chunks (16)
    int tc = blockIdx.x % ntc, jc = blockIdx.x / ntc; // jc in 0..7
    int tid = threadIdx.x;
    cudaGridDependencySynchronize();
    if (tid < 128) w[tid] = scg[(long)b * S + tc * 128 + tid];
    __syncthreads();

    int tg = tid >> 5, jj = tid & 31;                 // 8 token-partitions x 32 j4
    int j4 = jc * 32 + jj;
    const float4* xb = (const float4*)x + ((long)b * S + tc * 128) * 256;
    float4 acc = make_float4(0.f, 0.f, 0.f, 0.f);
#pragma unroll 8
    for (int t = tg; t < 128; t += 8) {
        float p = w[t];
        float4 xv = xb[(long)t * 256 + j4];
        acc.x = fmaf(p, xv.x, acc.x);
        acc.y = fmaf(p, xv.y, acc.y);
        acc.z = fmaf(p, xv.z, acc.z);
        acc.w = fmaf(p, xv.w, acc.w);
    }
    redb[tg][jj] = acc;
    __syncthreads();
    if (tg == 0) {
        float4 t0 = redb[0][jj];
#pragma unroll
        for (int p = 1; p < 8; p++) {
            float4 v = redb[p][jj];
            t0.x += v.x; t0.y += v.y; t0.z += v.z; t0.w += v.w;
        }
        float* dst = &xw[(long)b * Dm + j4 * 4];
        atomicAdd(dst + 0, t0.x);
        atomicAdd(dst + 1, t0.y);
        atomicAdd(dst + 2, t0.z);
        atomicAdd(dst + 3, t0.w);
    }
}

// ---------------- r = LN1(accV/Z + bv + x0); reset accV, xw, Z ---------------
__global__ void __launch_bounds__(1024) k_ln1(float* __restrict__ acc,
                                              const float* __restrict__ x, long xstride,
                                              const float* __restrict__ bv,
                                              const float* __restrict__ g1,
                                              const float* __restrict__ b1,
                                              float* __restrict__ xwreset,
                                              float* __restrict__ Zg,
                                              float* __restrict__ r) {
    int b = blockIdx.x, j = threadIdx.x;
    __shared__ float sbuf[32];
    float gg = g1[j], bb = b1[j], bvj = bv[j];
    float x0j = x[(long)b * xstride + j];
    cudaGridDependencySynchronize();
    float zinv = 1.f / Zg[b];
    float v = fmaf(acc[(long)b * Dm + j], zinv, bvj + x0j);
    acc[(long)b * Dm + j] = 0.f;                      // reset for next replay
    xwreset[(long)b * Dm + j] = 0.f;                  // gemv(Wv) upstream done
    if (j == 0) Zg[b] = 0.f;
    float sum = blk_reduce(v, sbuf);
    float sq  = blk_reduce(v * v, sbuf);
    float mu  = sum * (1.f / Dm);
    float var = sq * (1.f / Dm) - mu * mu;
    float rstd = rsqrtf(var + 1e-5f);
    r[(long)b * Dm + j] = (v - mu) * rstd * gg + bb;
}

// ---------------- h = LN2(relu(accD + bd) + r); logits; reset accD -----------
__global__ void __launch_bounds__(1024) k_ln2(float* __restrict__ acc,
                                              const float* __restrict__ bd,
                                              const float* __restrict__ r,
                                              const float* __restrict__ g2,
                                              const float* __restrict__ b2,
                                              const float* __restrict__ Wc,
                                              const float* __restrict__ bc,
                                              float* __restrict__ out) {
    int b = blockIdx.x, j = threadIdx.x;
    __shared__ float sbuf[32];
    float gg = g2[j], bb = b2[j], bdj = bd[j];
    float w0 = Wc[j * 2 + 0], w1 = Wc[j * 2 + 1];
    cudaGridDependencySynchronize();
    float v = fmaxf(acc[(long)b * Dm + j] + bdj, 0.f) + r[(long)b * Dm + j];
    acc[(long)b * Dm + j] = 0.f;                      // reset for next replay
    float sum = blk_reduce(v, sbuf);
    float sq  = blk_reduce(v * v, sbuf);
    float mu  = sum * (1.f / Dm);
    float var = sq * (1.f / Dm) - mu * mu;
    float rstd = rsqrtf(var + 1e-5f);
    float h = (v - mu) * rstd * gg + bb;
    float l0 = blk_reduce(h * w0, sbuf);
    float l1 = blk_reduce(h * w1, sbuf);
    if (j == 0) {
        out[b * 2 + 0] = l0 + bc[0];
        out[b * 2 + 1] = l1 + bc[1];
    }
}

// ---------------- host --------------------------------------------------------
static void launch_ex(const void* fn, dim3 grid, dim3 block, void** args, bool pdl) {
    cudaLaunchConfig_t cfg = {};
    cfg.gridDim = grid;
    cfg.blockDim = block;
    cfg.dynamicSmemBytes = 0;
    cfg.stream = 0;
    cudaLaunchAttribute attr[1];
    attr[0].id = cudaLaunchAttributeProgrammaticStreamSerialization;
    attr[0].val.programmaticStreamSerializationAllowed = 1;
    cfg.attrs = attr;
    cfg.numAttrs = pdl ? 1 : 0;
    cudaLaunchKernelExC(&cfg, fn, args);
}

extern "C" void kernel_launch(void* const* d_in, const int* in_sizes, int n_in,
                              void* d_out, int out_size) {
    const float* x  = (const float*)d_in[0];
    const float* Wq = (const float*)d_in[1];
    const float* bq = (const float*)d_in[2];
    const float* Wk = (const float*)d_in[3];
    // d_in[4] = bk: constant over t in scores -> cancels in softmax; unused.
    const float* Wv = (const float*)d_in[5];
    const float* bv = (const float*)d_in[6];
    const float* Wd = (const float*)d_in[7];
    const float* bd = (const float*)d_in[8];
    const float* g1 = (const float*)d_in[9];
    const float* b1 = (const float*)d_in[10];
    const float* g2 = (const float*)d_in[11];
    const float* b2 = (const float*)d_in[12];
    const float* Wc = (const float*)d_in[13];
    const float* bc = (const float*)d_in[14];
    float* out = (float*)d_out;

    int  B   = out_size / 2;                       // 8
    long xsz = (long)in_sizes[0];
    int  S   = (int)(xsz / ((long)B * Dm));        // 2048
    long xstride = (long)S * Dm;

    float *q0, *u, *xw, *r, *accV, *accD, *sc, *Z;
    cudaGetSymbolAddress((void**)&q0,   g_q0);
    cudaGetSymbolAddress((void**)&u,    g_u);
    cudaGetSymbolAddress((void**)&xw,   g_xw);
    cudaGetSymbolAddress((void**)&r,    g_r);
    cudaGetSymbolAddress((void**)&accV, g_accV);
    cudaGetSymbolAddress((void**)&accD, g_accD);
    cudaGetSymbolAddress((void**)&sc,   g_sc);
    cudaGetSymbolAddress((void**)&Z,    g_Z);

    // 1. q0 += x0 @ Wq   (first kernel: no PDL wait; starts loading at t=0)
    {
        void* a[] = {(void*)&x, (void*)&xstride, (void*)&Wq, (void*)&q0, (void*)&B};
        launch_ex((const void*)gemv_pdl, dim3(8, 64), dim3(128), a, false);
    }
    // 2. u = Wk @ (q0 + bq)
    {
        void* a[] = {(void*)&Wk, (void*)&q0, (void*)&bq, (void*)&u};
        launch_ex((const void*)k2_u, dim3(Dm / 4), dim3(128), a, true);
    }
    // 3. exp'd scores + Z (also zeroes q0 for next replay)
    {
        void* a[] = {(void*)&x, (void*)&u, (void*)&q0, (void*)&sc, (void*)&Z, (void*)&S};
        launch_ex((const void*)k3a, dim3(S / 16, B), dim3(256), a, true);
    }
    // 4. weighted accumulate -> xw (unnormalized)
    {
        void* a[] = {(void*)&x, (void*)&sc, (void*)&xw, (void*)&S};
        launch_ex((const void*)k3b, dim3((S / 128) * 8, B), dim3(256), a, true);
    }
    // 5. accV += xw @ Wv
    {
        long st = Dm;
        void* a[] = {(void*)&xw, (void*)&st, (void*)&Wv, (void*)&accV, (void*)&B};
        launch_ex((const void*)gemv_pdl, dim3(8, 64), dim3(128), a, true);
    }
    // 6. r = LN1(accV/Z + bv + x0); zero accV, xw, Z
    {
        void* a[] = {(void*)&accV, (void*)&x, (void*)&xstride, (void*)&bv,
                     (void*)&g1, (void*)&b1, (void*)&xw, (void*)&Z, (void*)&r};
        launch_ex((const void*)k_ln1, dim3(B), dim3(1024), a, true);
    }
    // 7. accD += r @ Wd
    {
        long st = Dm;
        void* a[] = {(void*)&r, (void*)&st, (void*)&Wd, (void*)&accD, (void*)&B};
        launch_ex((const void*)gemv_pdl, dim3(8, 64), dim3(128), a, true);
    }
    // 8. out = LN2(relu(accD + bd) + r) @ Wc + bc; zero accD
    {
        void* a[] = {(void*)&accD, (void*)&bd, (void*)&r, (void*)&g2, (void*)&b2,
                     (void*)&Wc, (void*)&bc, (void*)&out};
        launch_ex((const void*)k_ln2, dim3(B), dim3(1024), a, true);
    }
}

// round 15
// speedup vs baseline: 1.0643x; 1.0589x over previous
#include <cuda_runtime.h>

#define Dm 1024
#define MAXB 8
#define SMAX 4096

// ---------------- scratch (zero-init at load; consumers reset for replay) ---
__device__ float g_q0[MAXB * Dm];              // Wq acc (zeroed by k3a)
__device__ float g_u[MAXB * Dm];               // overwritten fully by k2_u
__device__ float g_xw[MAXB * Dm];              // k3b acc (zeroed by k_ln1)
__device__ float g_Z[MAXB];                    // softmax denominators (zeroed by k_ln1)
__device__ float g_r[MAXB * Dm];               // overwritten fully by k_ln1
__device__ float g_accV[MAXB * Dm];            // Wv acc (zeroed by k_ln1)
__device__ float g_accD[MAXB * Dm];            // Wd acc (zeroed by k_ln2)
__device__ float g_sc[MAXB * SMAX];            // exp'd scores (overwritten by k3a)

// ---------------- block reductions ------------------------------------------
__device__ __forceinline__ float blk_reduce(float v, volatile float* sbuf) {
    int lane = threadIdx.x & 31, w = threadIdx.x >> 5;
#pragma unroll
    for (int o = 16; o; o >>= 1) v += __shfl_xor_sync(0xffffffffu, v, o);
    __syncthreads();
    if (lane == 0) sbuf[w] = v;
    __syncthreads();
    int nw = blockDim.x >> 5;
    if (w == 0) {
        float r = (lane < nw) ? sbuf[lane] : 0.f;
#pragma unroll
        for (int o = 16; o; o >>= 1) r += __shfl_xor_sync(0xffffffffu, r, o);
        if (lane == 0) sbuf[0] = r;
    }
    __syncthreads();
    return sbuf[0];
}

// ---------------- PDL skinny GEMV (R11 config): acc[b,j] += A[b,d0:d0+32]@W --
// grid (8, 32), block 128 (256 blocks). W tile preloaded to regs BEFORE
// gridsync. Target buffer must be zero on entry.
__global__ void __launch_bounds__(128) gemv_pdl(const float* __restrict__ A,
                                                long astride,
                                                const float* __restrict__ W,
                                                float* __restrict__ accout, int B) {
    __shared__ float as[MAXB][32];
    int tid = threadIdx.x;
    int j  = blockIdx.x * 128 + tid;
    int d0 = blockIdx.y * 32;
    float wv[32];
#pragma unroll
    for (int dd = 0; dd < 32; dd++) wv[dd] = W[(long)(d0 + dd) * Dm + j];
    cudaGridDependencySynchronize();
    for (int i = tid; i < MAXB * 32; i += 128) {
        int b = i >> 5, dd = i & 31;
        as[b][dd] = (b < B) ? A[(long)b * astride + d0 + dd] : 0.f;
    }
    __syncthreads();
    float acc[MAXB];
#pragma unroll
    for (int b = 0; b < MAXB; b++) acc[b] = 0.f;
#pragma unroll
    for (int dd = 0; dd < 32; dd++) {
#pragma unroll
        for (int b = 0; b < MAXB; b++) acc[b] = fmaf(as[b][dd], wv[dd], acc[b]);
    }
    for (int b = 0; b < B; b++)
        atomicAdd(&accout[(long)b * Dm + j], acc[b]);
}

// ---------------- u[b,d] = Wk[d,:] . (q0[b,:] + bq) (R11 config) -------------
// 128 blocks x 8 warps (1 row each). Wk row preloaded to regs before gridsync.
__global__ void __launch_bounds__(256) k2_u(const float* __restrict__ Wk,
                                            const float* __restrict__ q0g,
                                            const float* __restrict__ bq,
                                            float* __restrict__ u) {
    __shared__ float4 q0s[MAXB * 256];               // 32 KB
    int wid = threadIdx.x >> 5, lane = threadIdx.x & 31;
    int d = blockIdx.x * 8 + wid;
    const float4* wrow = (const float4*)(Wk + (long)d * Dm);
    float4 wv[8];
#pragma unroll
    for (int i = 0; i < 8; i++) wv[i] = wrow[lane + 32 * i];
    cudaGridDependencySynchronize();
    for (int i = threadIdx.x; i < MAXB * 256; i += 256) {
        float4 q = ((const float4*)q0g)[i];
        float4 bb = ((const float4*)bq)[i & 255];
        q.x += bb.x; q.y += bb.y; q.z += bb.z; q.w += bb.w;
        q0s[i] = q;
    }
    __syncthreads();
    float acc[MAXB];
#pragma unroll
    for (int b = 0; b < MAXB; b++) acc[b] = 0.f;
#pragma unroll
    for (int i = 0; i < 8; i++) {
#pragma unroll
        for (int b = 0; b < MAXB; b++) {
            float4 q = q0s[b * 256 + lane + 32 * i];
            acc[b] += wv[i].x * q.x + wv[i].y * q.y + wv[i].z * q.z + wv[i].w * q.w;
        }
    }
#pragma unroll
    for (int b = 0; b < MAXB; b++)
#pragma unroll
        for (int o = 16; o; o >>= 1)
            acc[b] += __shfl_xor_sync(0xffffffffu, acc[b], o);
    if (lane == 0)
#pragma unroll
        for (int b = 0; b < MAXB; b++) u[(long)b * Dm + d] = acc[b];
}

// ---------------- k3a: score stream, stores p = exp(score); Z atomics -------
// grid (S/16, B) = 1024 blocks, 256 thr, 2 tokens/warp. No-max softmax:
// scores ~N(0,1) so raw exp is fp32-safe (validated R12/R14, rel_err ~6e-7).
__global__ void __launch_bounds__(256) k3a(const float* __restrict__ x,
                                           const float* __restrict__ ug,
                                           float* __restrict__ q0reset,
                                           float* __restrict__ sc,
                                           float* __restrict__ Zg, int S) {
    __shared__ float zp[8];
    int b = blockIdx.y;
    int tid = threadIdx.x, wid = tid >> 5, lane = tid & 31;
    int tbase = blockIdx.x * 16 + wid * 2;
    const float4* x0 = (const float4*)x + ((long)b * S + tbase) * 256;
#pragma unroll
    for (int k = 0; k < 2; k++)
#pragma unroll
        for (int i = 0; i < 8; i++)
            asm volatile("prefetch.global.L2 [%0];" :: "l"(x0 + k * 256 + lane + 32 * i));
    cudaGridDependencySynchronize();
    if (blockIdx.x == 0)                              // zero q0[b,:] for next run
        ((float4*)q0reset)[b * 256 + tid] = make_float4(0.f, 0.f, 0.f, 0.f);
    const float4* ub = (const float4*)(ug + (long)b * Dm);
    float4 uv[8];
#pragma unroll
    for (int i = 0; i < 8; i++) uv[i] = __ldg(ub + lane + 32 * i);
    float zsum = 0.f;                                 // identical across lanes
#pragma unroll
    for (int k = 0; k < 2; k++) {
        const float4* xr = x0 + (long)k * 256;
        float d = 0.f;
#pragma unroll
        for (int i = 0; i < 8; i++) {
            float4 xv = xr[lane + 32 * i];
            d += xv.x * uv[i].x + xv.y * uv[i].y + xv.z * uv[i].z + xv.w * uv[i].w;
        }
#pragma unroll
        for (int o = 16; o; o >>= 1) d += __shfl_xor_sync(0xffffffffu, d, o);
        float p = __expf(d * 0.03125f);               // 1/sqrt(1024)
        zsum += p;
        if (lane == 0) sc[(long)b * S + tbase + k] = p;
    }
    if (lane == 0) zp[wid] = zsum;                    // warp's 2-token sum
    __syncthreads();
    if (tid == 0) {
        float zb = 0.f;
#pragma unroll
        for (int w = 0; w < 8; w++) zb += zp[w];
        atomicAdd(&Zg[b], zb);
    }
}

// ---------------- k3b: weighted accumulate (weights precomputed) ------------
// grid ((S/128)*8, B) = 1024 blocks, 256 thr. No reductions, no score rescan.
__global__ void __launch_bounds__(256) k3b(const float* __restrict__ x,
                                           const float* __restrict__ scg,
                                           float* __restrict__ xw, int S) {
    __shared__ float w[128];
    __shared__ float4 redb[8][32];
    int b = blockIdx.y;
    int ntc = S >> 7;                                 // 128-token chunks (16)
    int tc = blockIdx.x % ntc, jc = blockIdx.x / ntc; // jc in 0..7
    int tid = threadIdx.x;
    cudaGridDependencySynchronize();
    if (tid < 128) w[tid] = scg[(long)b * S + tc * 128 + tid];
    __syncthreads();

    int tg = tid >> 5, jj = tid & 31;                 // 8 token-partitions x 32 j4
    int j4 = jc * 32 + jj;
    const float4* xb = (const float4*)x + ((long)b * S + tc * 128) * 256;
    float4 acc = make_float4(0.f, 0.f, 0.f, 0.f);
#pragma unroll 8
    for (int t = tg; t < 128; t += 8) {
        float p = w[t];
        float4 xv = xb[(long)t * 256 + j4];
        acc.x = fmaf(p, xv.x, acc.x);
        acc.y = fmaf(p, xv.y, acc.y);
        acc.z = fmaf(p, xv.z, acc.z);
        acc.w = fmaf(p, xv.w, acc.w);
    }
    redb[tg][jj] = acc;
    __syncthreads();
    if (tg == 0) {
        float4 t0 = redb[0][jj];
#pragma unroll
        for (int p = 1; p < 8; p++) {
            float4 v = redb[p][jj];
            t0.x += v.x; t0.y += v.y; t0.z += v.z; t0.w += v.w;
        }
        float* dst = &xw[(long)b * Dm + j4 * 4];
        atomicAdd(dst + 0, t0.x);
        atomicAdd(dst + 1, t0.y);
        atomicAdd(dst + 2, t0.z);
        atomicAdd(dst + 3, t0.w);
    }
}

// ---------------- r = LN1(accV/Z + bv + x0); reset accV, xw, Z ---------------
__global__ void __launch_bounds__(1024) k_ln1(float* __restrict__ acc,
                                              const float* __restrict__ x, long xstride,
                                              const float* __restrict__ bv,
                                              const float* __restrict__ g1,
                                              const float* __restrict__ b1,
                                              float* __restrict__ xwreset,
                                              float* __restrict__ Zg,
                                              float* __restrict__ r) {
    int b = blockIdx.x, j = threadIdx.x;
    __shared__ float sbuf[32];
    float gg = g1[j], bb = b1[j], bvj = bv[j];
    float x0j = x[(long)b * xstride + j];
    cudaGridDependencySynchronize();
    float zinv = 1.f / Zg[b];
    float v = fmaf(acc[(long)b * Dm + j], zinv, bvj + x0j);
    acc[(long)b * Dm + j] = 0.f;                      // reset for next replay
    xwreset[(long)b * Dm + j] = 0.f;                  // gemv(Wv) upstream done
    if (j == 0) Zg[b] = 0.f;
    float sum = blk_reduce(v, sbuf);
    float sq  = blk_reduce(v * v, sbuf);
    float mu  = sum * (1.f / Dm);
    float var = sq * (1.f / Dm) - mu * mu;
    float rstd = rsqrtf(var + 1e-5f);
    r[(long)b * Dm + j] = (v - mu) * rstd * gg + bb;
}

// ---------------- h = LN2(relu(accD + bd) + r); logits; reset accD -----------
__global__ void __launch_bounds__(1024) k_ln2(float* __restrict__ acc,
                                              const float* __restrict__ bd,
                                              const float* __restrict__ r,
                                              const float* __restrict__ g2,
                                              const float* __restrict__ b2,
                                              const float* __restrict__ Wc,
                                              const float* __restrict__ bc,
                                              float* __restrict__ out) {
    int b = blockIdx.x, j = threadIdx.x;
    __shared__ float sbuf[32];
    float gg = g2[j], bb = b2[j], bdj = bd[j];
    float w0 = Wc[j * 2 + 0], w1 = Wc[j * 2 + 1];
    cudaGridDependencySynchronize();
    float v = fmaxf(acc[(long)b * Dm + j] + bdj, 0.f) + r[(long)b * Dm + j];
    acc[(long)b * Dm + j] = 0.f;                      // reset for next replay
    float sum = blk_reduce(v, sbuf);
    float sq  = blk_reduce(v * v, sbuf);
    float mu  = sum * (1.f / Dm);
    float var = sq * (1.f / Dm) - mu * mu;
    float rstd = rsqrtf(var + 1e-5f);
    float h = (v - mu) * rstd * gg + bb;
    float l0 = blk_reduce(h * w0, sbuf);
    float l1 = blk_reduce(h * w1, sbuf);
    if (j == 0) {
        out[b * 2 + 0] = l0 + bc[0];
        out[b * 2 + 1] = l1 + bc[1];
    }
}

// ---------------- host --------------------------------------------------------
static void launch_ex(const void* fn, dim3 grid, dim3 block, void** args, bool pdl) {
    cudaLaunchConfig_t cfg = {};
    cfg.gridDim = grid;
    cfg.blockDim = block;
    cfg.dynamicSmemBytes = 0;
    cfg.stream = 0;
    cudaLaunchAttribute attr[1];
    attr[0].id = cudaLaunchAttributeProgrammaticStreamSerialization;
    attr[0].val.programmaticStreamSerializationAllowed = 1;
    cfg.attrs = attr;
    cfg.numAttrs = pdl ? 1 : 0;
    cudaLaunchKernelExC(&cfg, fn, args);
}

extern "C" void kernel_launch(void* const* d_in, const int* in_sizes, int n_in,
                              void* d_out, int out_size) {
    const float* x  = (const float*)d_in[0];
    const float* Wq = (const float*)d_in[1];
    const float* bq = (const float*)d_in[2];
    const float* Wk = (const float*)d_in[3];
    // d_in[4] = bk: constant over t in scores -> cancels in softmax; unused.
    const float* Wv = (const float*)d_in[5];
    const float* bv = (const float*)d_in[6];
    const float* Wd = (const float*)d_in[7];
    const float* bd = (const float*)d_in[8];
    const float* g1 = (const float*)d_in[9];
    const float* b1 = (const float*)d_in[10];
    const float* g2 = (const float*)d_in[11];
    const float* b2 = (const float*)d_in[12];
    const float* Wc = (const float*)d_in[13];
    const float* bc = (const float*)d_in[14];
    float* out = (float*)d_out;

    int  B   = out_size / 2;                       // 8
    long xsz = (long)in_sizes[0];
    int  S   = (int)(xsz / ((long)B * Dm));        // 2048
    long xstride = (long)S * Dm;

    float *q0, *u, *xw, *r, *accV, *accD, *sc, *Z;
    cudaGetSymbolAddress((void**)&q0,   g_q0);
    cudaGetSymbolAddress((void**)&u,    g_u);
    cudaGetSymbolAddress((void**)&xw,   g_xw);
    cudaGetSymbolAddress((void**)&r,    g_r);
    cudaGetSymbolAddress((void**)&accV, g_accV);
    cudaGetSymbolAddress((void**)&accD, g_accD);
    cudaGetSymbolAddress((void**)&sc,   g_sc);
    cudaGetSymbolAddress((void**)&Z,    g_Z);

    // 1. q0 += x0 @ Wq   (first kernel: no PDL wait; starts loading at t=0)
    {
        void* a[] = {(void*)&x, (void*)&xstride, (void*)&Wq, (void*)&q0, (void*)&B};
        launch_ex((const void*)gemv_pdl, dim3(8, 32), dim3(128), a, false);
    }
    // 2. u = Wk @ (q0 + bq)
    {
        void* a[] = {(void*)&Wk, (void*)&q0, (void*)&bq, (void*)&u};
        launch_ex((const void*)k2_u, dim3(Dm / 8), dim3(256), a, true);
    }
    // 3. exp'd scores + Z (also zeroes q0 for next replay)
    {
        void* a[] = {(void*)&x, (void*)&u, (void*)&q0, (void*)&sc, (void*)&Z, (void*)&S};
        launch_ex((const void*)k3a, dim3(S / 16, B), dim3(256), a, true);
    }
    // 4. weighted accumulate -> xw (unnormalized)
    {
        void* a[] = {(void*)&x, (void*)&sc, (void*)&xw, (void*)&S};
        launch_ex((const void*)k3b, dim3((S / 128) * 8, B), dim3(256), a, true);
    }
    // 5. accV += xw @ Wv
    {
        long st = Dm;
        void* a[] = {(void*)&xw, (void*)&st, (void*)&Wv, (void*)&accV, (void*)&B};
        launch_ex((const void*)gemv_pdl, dim3(8, 32), dim3(128), a, true);
    }
    // 6. r = LN1(accV/Z + bv + x0); zero accV, xw, Z
    {
        void* a[] = {(void*)&accV, (void*)&x, (void*)&xstride, (void*)&bv,
                     (void*)&g1, (void*)&b1, (void*)&xw, (void*)&Z, (void*)&r};
        launch_ex((const void*)k_ln1, dim3(B), dim3(1024), a, true);
    }
    // 7. accD += r @ Wd
    {
        long st = Dm;
        void* a[] = {(void*)&r, (void*)&st, (void*)&Wd, (void*)&accD, (void*)&B};
        launch_ex((const void*)gemv_pdl, dim3(8, 32), dim3(128), a, true);
    }
    // 8. out = LN2(relu(accD + bd) + r) @ Wc + bc; zero accD
    {
        void* a[] = {(void*)&accD, (void*)&bd, (void*)&r, (void*)&g2, (void*)&b2,
                     (void*)&Wc, (void*)&bc, (void*)&out};
        launch_ex((const void*)k_ln2, dim3(B), dim3(1024), a, true);
    }
}

// round 16
// speedup vs baseline: 1.2027x; 1.1300x over previous
#include <cuda_runtime.h>

#define Dm 1024
#define MAXB 8
#define SMAX 4096

// ---------------- scratch (zero-init at load; consumers reset for replay) ---
__device__ float g_q0[MAXB * Dm];              // Wq acc (zeroed by k3a)
__device__ float g_u[MAXB * Dm];               // overwritten fully by k2_u
__device__ float g_xw[MAXB * Dm];              // k3b acc (zeroed by k_ln1)
__device__ float g_Z[MAXB];                    // softmax denominators (zeroed by k_ln1)
__device__ float g_r[MAXB * Dm];               // overwritten fully by k_ln1
__device__ float g_accV[MAXB * Dm];            // Wv acc (zeroed by k_ln1)
__device__ float g_accD[MAXB * Dm];            // Wd acc (zeroed by k_ln2)
__device__ float g_sc[MAXB * SMAX];            // exp'd scores (overwritten by k3a)

// ---------------- paired block reduction (two sums, one barrier set) --------
__device__ __forceinline__ void blk_reduce2(float& a, float& b, volatile float* sbuf) {
    int lane = threadIdx.x & 31, w = threadIdx.x >> 5;
#pragma unroll
    for (int o = 16; o; o >>= 1) {
        a += __shfl_xor_sync(0xffffffffu, a, o);
        b += __shfl_xor_sync(0xffffffffu, b, o);
    }
    __syncthreads();
    if (lane == 0) { sbuf[w * 2] = a; sbuf[w * 2 + 1] = b; }
    __syncthreads();
    int nw = blockDim.x >> 5;
    if (w == 0) {
        float ra = (lane < nw) ? sbuf[lane * 2]     : 0.f;
        float rb = (lane < nw) ? sbuf[lane * 2 + 1] : 0.f;
#pragma unroll
        for (int o = 16; o; o >>= 1) {
            ra += __shfl_xor_sync(0xffffffffu, ra, o);
            rb += __shfl_xor_sync(0xffffffffu, rb, o);
        }
        if (lane == 0) { sbuf[0] = ra; sbuf[1] = rb; }
    }
    __syncthreads();
    a = sbuf[0]; b = sbuf[1];
}

// ---------------- PDL skinny GEMV (R11 config): acc[b,j] += A[b,d0:d0+32]@W --
// grid (8, 32), block 128 (256 blocks). W tile preloaded to regs BEFORE
// gridsync. Target buffer must be zero on entry.
__global__ void __launch_bounds__(128) gemv_pdl(const float* __restrict__ A,
                                                long astride,
                                                const float* __restrict__ W,
                                                float* __restrict__ accout, int B) {
    __shared__ float as[MAXB][32];
    int tid = threadIdx.x;
    int j  = blockIdx.x * 128 + tid;
    int d0 = blockIdx.y * 32;
    float wv[32];
#pragma unroll
    for (int dd = 0; dd < 32; dd++) wv[dd] = W[(long)(d0 + dd) * Dm + j];
    cudaGridDependencySynchronize();
    for (int i = tid; i < MAXB * 32; i += 128) {
        int b = i >> 5, dd = i & 31;
        as[b][dd] = (b < B) ? A[(long)b * astride + d0 + dd] : 0.f;
    }
    __syncthreads();
    float acc[MAXB];
#pragma unroll
    for (int b = 0; b < MAXB; b++) acc[b] = 0.f;
#pragma unroll
    for (int dd = 0; dd < 32; dd++) {
#pragma unroll
        for (int b = 0; b < MAXB; b++) acc[b] = fmaf(as[b][dd], wv[dd], acc[b]);
    }
    for (int b = 0; b < B; b++)
        atomicAdd(&accout[(long)b * Dm + j], acc[b]);
}

// ---------------- u[b,d] = Wk[d,:] . (q0[b,:] + bq) --------------------------
// 128 blocks x 8 warps (1 row each). Wk row + bq preloaded before gridsync.
__global__ void __launch_bounds__(256) k2_u(const float* __restrict__ Wk,
                                            const float* __restrict__ q0g,
                                            const float* __restrict__ bq,
                                            float* __restrict__ u) {
    __shared__ float4 q0s[MAXB * 256];               // 32 KB
    __shared__ float4 bqs[256];                      // 4 KB
    int wid = threadIdx.x >> 5, lane = threadIdx.x & 31;
    int d = blockIdx.x * 8 + wid;
    const float4* wrow = (const float4*)(Wk + (long)d * Dm);
    float4 wv[8];
#pragma unroll
    for (int i = 0; i < 8; i++) wv[i] = wrow[lane + 32 * i];
    bqs[threadIdx.x] = ((const float4*)bq)[threadIdx.x];   // pre-sync (input)
    cudaGridDependencySynchronize();
    for (int i = threadIdx.x; i < MAXB * 256; i += 256) {
        float4 q = ((const float4*)q0g)[i];
        float4 bb = bqs[i & 255];
        q.x += bb.x; q.y += bb.y; q.z += bb.z; q.w += bb.w;
        q0s[i] = q;
    }
    __syncthreads();
    float acc[MAXB];
#pragma unroll
    for (int b = 0; b < MAXB; b++) acc[b] = 0.f;
#pragma unroll
    for (int i = 0; i < 8; i++) {
#pragma unroll
        for (int b = 0; b < MAXB; b++) {
            float4 q = q0s[b * 256 + lane + 32 * i];
            acc[b] += wv[i].x * q.x + wv[i].y * q.y + wv[i].z * q.z + wv[i].w * q.w;
        }
    }
#pragma unroll
    for (int b = 0; b < MAXB; b++)
#pragma unroll
        for (int o = 16; o; o >>= 1)
            acc[b] += __shfl_xor_sync(0xffffffffu, acc[b], o);
    if (lane == 0)
#pragma unroll
        for (int b = 0; b < MAXB; b++) u[(long)b * Dm + d] = acc[b];
}

// ---------------- k3a: score stream, stores p = exp(score); Z atomics -------
// grid (S/16, B) = 1024 blocks, 256 thr, 2 tokens/warp. No-max softmax:
// scores ~N(0,1) so raw exp is fp32-safe (validated R12/R14/R15, ~6e-7).
__global__ void __launch_bounds__(256) k3a(const float* __restrict__ x,
                                           const float* __restrict__ ug,
                                           float* __restrict__ q0reset,
                                           float* __restrict__ sc,
                                           float* __restrict__ Zg, int S) {
    __shared__ float zp[8];
    int b = blockIdx.y;
    int tid = threadIdx.x, wid = tid >> 5, lane = tid & 31;
    int tbase = blockIdx.x * 16 + wid * 2;
    const float4* x0 = (const float4*)x + ((long)b * S + tbase) * 256;
#pragma unroll
    for (int k = 0; k < 2; k++)
#pragma unroll
        for (int i = 0; i < 8; i++)
            asm volatile("prefetch.global.L2 [%0];" :: "l"(x0 + k * 256 + lane + 32 * i));
    cudaGridDependencySynchronize();
    if (blockIdx.x == 0)                              // zero q0[b,:] for next run
        ((float4*)q0reset)[b * 256 + tid] = make_float4(0.f, 0.f, 0.f, 0.f);
    const float4* ub = (const float4*)(ug + (long)b * Dm);
    float4 uv[8];
#pragma unroll
    for (int i = 0; i < 8; i++) uv[i] = __ldg(ub + lane + 32 * i);
    float zsum = 0.f;
#pragma unroll
    for (int k = 0; k < 2; k++) {
        const float4* xr = x0 + (long)k * 256;
        float d = 0.f;
#pragma unroll
        for (int i = 0; i < 8; i++) {
            float4 xv = xr[lane + 32 * i];
            d += xv.x * uv[i].x + xv.y * uv[i].y + xv.z * uv[i].z + xv.w * uv[i].w;
        }
#pragma unroll
        for (int o = 16; o; o >>= 1) d += __shfl_xor_sync(0xffffffffu, d, o);
        float p = __expf(d * 0.03125f);               // 1/sqrt(1024)
        zsum += p;
        if (lane == 0) sc[(long)b * S + tbase + k] = p;
    }
    if (lane == 0) zp[wid] = zsum;
    __syncthreads();
    if (tid == 0) {
        float zb = 0.f;
#pragma unroll
        for (int w = 0; w < 8; w++) zb += zp[w];
        atomicAdd(&Zg[b], zb);
    }
}

// ---------------- k3b: weighted accumulate (weights precomputed) ------------
// grid ((S/128)*8, B) = 1024 blocks, 256 thr. Fully unrolled: 16 LDG.128
// in flight per thread slice.
__global__ void __launch_bounds__(256) k3b(const float* __restrict__ x,
                                           const float* __restrict__ scg,
                                           float* __restrict__ xw, int S) {
    __shared__ float w[128];
    __shared__ float4 redb[8][32];
    int b = blockIdx.y;
    int ntc = S >> 7;                                 // 128-token chunks (16)
    int tc = blockIdx.x % ntc, jc = blockIdx.x / ntc; // jc in 0..7
    int tid = threadIdx.x;
    cudaGridDependencySynchronize();
    if (tid < 128) w[tid] = scg[(long)b * S + tc * 128 + tid];
    __syncthreads();

    int tg = tid >> 5, jj = tid & 31;                 // 8 token-partitions x 32 j4
    int j4 = jc * 32 + jj;
    const float4* xb = (const float4*)x + ((long)b * S + tc * 128) * 256;
    float4 acc = make_float4(0.f, 0.f, 0.f, 0.f);
#pragma unroll
    for (int it = 0; it < 16; it++) {                 // full unroll: 16 in flight
        int t = tg + it * 8;
        float p = w[t];
        float4 xv = xb[(long)t * 256 + j4];
        acc.x = fmaf(p, xv.x, acc.x);
        acc.y = fmaf(p, xv.y, acc.y);
        acc.z = fmaf(p, xv.z, acc.z);
        acc.w = fmaf(p, xv.w, acc.w);
    }
    redb[tg][jj] = acc;
    __syncthreads();
    if (tg == 0) {
        float4 t0 = redb[0][jj];
#pragma unroll
        for (int p = 1; p < 8; p++) {
            float4 v = redb[p][jj];
            t0.x += v.x; t0.y += v.y; t0.z += v.z; t0.w += v.w;
        }
        float* dst = &xw[(long)b * Dm + j4 * 4];
        atomicAdd(dst + 0, t0.x);
        atomicAdd(dst + 1, t0.y);
        atomicAdd(dst + 2, t0.z);
        atomicAdd(dst + 3, t0.w);
    }
}

// ---------------- r = LN1(accV/Z + bv + x0); reset accV, xw, Z ---------------
// 256 thr x 4 elems (float4). Paired reduction: 1 barrier set for sum+sq.
__global__ void __launch_bounds__(256) k_ln1(float* __restrict__ acc,
                                             const float* __restrict__ x, long xstride,
                                             const float* __restrict__ bv,
                                             const float* __restrict__ g1,
                                             const float* __restrict__ b1,
                                             float* __restrict__ xwreset,
                                             float* __restrict__ Zg,
                                             float* __restrict__ r) {
    int b = blockIdx.x, t = threadIdx.x;
    __shared__ float sbuf[64];
    // preloads independent of upstream (PDL overlap)
    float4 gg = ((const float4*)g1)[t];
    float4 bb = ((const float4*)b1)[t];
    float4 bvv = ((const float4*)bv)[t];
    float4 x0v = ((const float4*)(x + (long)b * xstride))[t];
    cudaGridDependencySynchronize();
    float zinv = 1.f / Zg[b];
    float4 a = ((const float4*)(acc + (long)b * Dm))[t];
    float4 v;
    v.x = fmaf(a.x, zinv, bvv.x + x0v.x);
    v.y = fmaf(a.y, zinv, bvv.y + x0v.y);
    v.z = fmaf(a.z, zinv, bvv.z + x0v.z);
    v.w = fmaf(a.w, zinv, bvv.w + x0v.w);
    ((float4*)(acc + (long)b * Dm))[t]      = make_float4(0.f, 0.f, 0.f, 0.f);
    ((float4*)(xwreset + (long)b * Dm))[t]  = make_float4(0.f, 0.f, 0.f, 0.f);
    if (t == 0) Zg[b] = 0.f;
    float s1 = v.x + v.y + v.z + v.w;
    float s2 = v.x * v.x + v.y * v.y + v.z * v.z + v.w * v.w;
    blk_reduce2(s1, s2, sbuf);
    float mu  = s1 * (1.f / Dm);
    float var = s2 * (1.f / Dm) - mu * mu;
    float rstd = rsqrtf(var + 1e-5f);
    float4 rv;
    rv.x = (v.x - mu) * rstd * gg.x + bb.x;
    rv.y = (v.y - mu) * rstd * gg.y + bb.y;
    rv.z = (v.z - mu) * rstd * gg.z + bb.z;
    rv.w = (v.w - mu) * rstd * gg.w + bb.w;
    ((float4*)(r + (long)b * Dm))[t] = rv;
}

// ---------------- h = LN2(relu(accD+bd)+r); logits; reset accD ---------------
// 256 thr x 4 elems. Two paired reductions total.
__global__ void __launch_bounds__(256) k_ln2(float* __restrict__ acc,
                                             const float* __restrict__ bd,
                                             const float* __restrict__ r,
                                             const float* __restrict__ g2,
                                             const float* __restrict__ b2,
                                             const float* __restrict__ Wc,
                                             const float* __restrict__ bc,
                                             float* __restrict__ out) {
    int b = blockIdx.x, t = threadIdx.x;
    __shared__ float sbuf[64];
    float4 gg  = ((const float4*)g2)[t];
    float4 bb  = ((const float4*)b2)[t];
    float4 bdv = ((const float4*)bd)[t];
    float4 wc0 = ((const float4*)Wc)[t * 2 + 0];      // (w0,w1) for elems 0,1
    float4 wc1 = ((const float4*)Wc)[t * 2 + 1];      // (w0,w1) for elems 2,3
    cudaGridDependencySynchronize();
    float4 a  = ((const float4*)(acc + (long)b * Dm))[t];
    float4 rv = ((const float4*)(r   + (long)b * Dm))[t];
    float4 v;
    v.x = fmaxf(a.x + bdv.x, 0.f) + rv.x;
    v.y = fmaxf(a.y + bdv.y, 0.f) + rv.y;
    v.z = fmaxf(a.z + bdv.z, 0.f) + rv.z;
    v.w = fmaxf(a.w + bdv.w, 0.f) + rv.w;
    ((float4*)(acc + (long)b * Dm))[t] = make_float4(0.f, 0.f, 0.f, 0.f);
    float s1 = v.x + v.y + v.z + v.w;
    float s2 = v.x * v.x + v.y * v.y + v.z * v.z + v.w * v.w;
    blk_reduce2(s1, s2, sbuf);
    float mu  = s1 * (1.f / Dm);
    float var = s2 * (1.f / Dm) - mu * mu;
    float rstd = rsqrtf(var + 1e-5f);
    float h0 = (v.x - mu) * rstd * gg.x + bb.x;
    float h1 = (v.y - mu) * rstd * gg.y + bb.y;
    float h2 = (v.z - mu) * rstd * gg.z + bb.z;
    float h3 = (v.w - mu) * rstd * gg.w + bb.w;
    float l0 = h0 * wc0.x + h1 * wc0.z + h2 * wc1.x + h3 * wc1.z;
    float l1 = h0 * wc0.y + h1 * wc0.w + h2 * wc1.y + h3 * wc1.w;
    blk_reduce2(l0, l1, sbuf);
    if (t == 0) {
        out[b * 2 + 0] = l0 + bc[0];
        out[b * 2 + 1] = l1 + bc[1];
    }
}

// ---------------- host --------------------------------------------------------
static void launch_ex(const void* fn, dim3 grid, dim3 block, void** args, bool pdl) {
    cudaLaunchConfig_t cfg = {};
    cfg.gridDim = grid;
    cfg.blockDim = block;
    cfg.dynamicSmemBytes = 0;
    cfg.stream = 0;
    cudaLaunchAttribute attr[1];
    attr[0].id = cudaLaunchAttributeProgrammaticStreamSerialization;
    attr[0].val.programmaticStreamSerializationAllowed = 1;
    cfg.attrs = attr;
    cfg.numAttrs = pdl ? 1 : 0;
    cudaLaunchKernelExC(&cfg, fn, args);
}

extern "C" void kernel_launch(void* const* d_in, const int* in_sizes, int n_in,
                              void* d_out, int out_size) {
    const float* x  = (const float*)d_in[0];
    const float* Wq = (const float*)d_in[1];
    const float* bq = (const float*)d_in[2];
    const float* Wk = (const float*)d_in[3];
    // d_in[4] = bk: constant over t in scores -> cancels in softmax; unused.
    const float* Wv = (const float*)d_in[5];
    const float* bv = (const float*)d_in[6];
    const float* Wd = (const float*)d_in[7];
    const float* bd = (const float*)d_in[8];
    const float* g1 = (const float*)d_in[9];
    const float* b1 = (const float*)d_in[10];
    const float* g2 = (const float*)d_in[11];
    const float* b2 = (const float*)d_in[12];
    const float* Wc = (const float*)d_in[13];
    const float* bc = (const float*)d_in[14];
    float* out = (float*)d_out;

    int  B   = out_size / 2;                       // 8
    long xsz = (long)in_sizes[0];
    int  S   = (int)(xsz / ((long)B * Dm));        // 2048
    long xstride = (long)S * Dm;

    float *q0, *u, *xw, *r, *accV, *accD, *sc, *Z;
    cudaGetSymbolAddress((void**)&q0,   g_q0);
    cudaGetSymbolAddress((void**)&u,    g_u);
    cudaGetSymbolAddress((void**)&xw,   g_xw);
    cudaGetSymbolAddress((void**)&r,    g_r);
    cudaGetSymbolAddress((void**)&accV, g_accV);
    cudaGetSymbolAddress((void**)&accD, g_accD);
    cudaGetSymbolAddress((void**)&sc,   g_sc);
    cudaGetSymbolAddress((void**)&Z,    g_Z);

    // 1. q0 += x0 @ Wq   (first kernel: no PDL wait; starts loading at t=0)
    {
        void* a[] = {(void*)&x, (void*)&xstride, (void*)&Wq, (void*)&q0, (void*)&B};
        launch_ex((const void*)gemv_pdl, dim3(8, 32), dim3(128), a, false);
    }
    // 2. u = Wk @ (q0 + bq)
    {
        void* a[] = {(void*)&Wk, (void*)&q0, (void*)&bq, (void*)&u};
        launch_ex((const void*)k2_u, dim3(Dm / 8), dim3(256), a, true);
    }
    // 3. exp'd scores + Z (also zeroes q0 for next replay)
    {
        void* a[] = {(void*)&x, (void*)&u, (void*)&q0, (void*)&sc, (void*)&Z, (void*)&S};
        launch_ex((const void*)k3a, dim3(S / 16, B), dim3(256), a, true);
    }
    // 4. weighted accumulate -> xw (unnormalized)
    {
        void* a[] = {(void*)&x, (void*)&sc, (void*)&xw, (void*)&S};
        launch_ex((const void*)k3b, dim3((S / 128) * 8, B), dim3(256), a, true);
    }
    // 5. accV += xw @ Wv
    {
        long st = Dm;
        void* a[] = {(void*)&xw, (void*)&st, (void*)&Wv, (void*)&accV, (void*)&B};
        launch_ex((const void*)gemv_pdl, dim3(8, 32), dim3(128), a, true);
    }
    // 6. r = LN1(accV/Z + bv + x0); zero accV, xw, Z
    {
        void* a[] = {(void*)&accV, (void*)&x, (void*)&xstride, (void*)&bv,
                     (void*)&g1, (void*)&b1, (void*)&xw, (void*)&Z, (void*)&r};
        launch_ex((const void*)k_ln1, dim3(B), dim3(256), a, true);
    }
    // 7. accD += r @ Wd
    {
        long st = Dm;
        void* a[] = {(void*)&r, (void*)&st, (void*)&Wd, (void*)&accD, (void*)&B};
        launch_ex((const void*)gemv_pdl, dim3(8, 32), dim3(128), a, true);
    }
    // 8. out = LN2(relu(accD + bd) + r) @ Wc + bc; zero accD
    {
        void* a[] = {(void*)&accD, (void*)&bd, (void*)&r, (void*)&g2, (void*)&b2,
                     (void*)&Wc, (void*)&bc, (void*)&out};
        launch_ex((const void*)k_ln2, dim3(B), dim3(256), a, true);
    }
}